// round 14
// baseline (speedup 1.0000x reference)
#include <cuda_runtime.h>
#include <cuda_bf16.h>
#include <cstdint>

#define TT 2
#define NN 4096
#define DD 1024
#define EE 8
#define OO 1024
#define NTOK (TT * NN)

// GEMM tiling: CTA 128x128, 8 warps of 32x64, BK=32, tf32, 2 CTAs/SM
#define BM 128
#define BN 128
#define BK 32
#define NCHUNK (DD / BK)       // 32
#define NTHREADS 256

#define ROWB 144               // 128B data + 16B pad -> conflict-free ldmatrix
#define OFF_B 18432            // A region = 128*144
#define STAGE_BYTES 36864
#define NSTAGE 3
#define HDR_BYTES 2048
#define SMEM_TOTAL (HDR_BYTES + NSTAGE * STAGE_BYTES)   // 112640 -> 2 CTAs/SM

#define GATE_SMEM ((DD * EE + 8 * DD) * 4)              // 65536: sWg + sX[8][DD]

// ---------------- device scratch ----------------
__device__ int      g_count[EE];                        // zeroed by combine tail each run
__device__ int      g_tok[EE][NTOK];
__device__ int      g_slot[EE][NTOK];
__device__ float    g_gate[EE][NTOK];
__device__ uint32_t g_xt[(size_t)NTOK * DD];            // tf32-rounded x  [token][k]
__device__ uint32_t g_wt[(size_t)EE * OO * DD];         // tf32-rounded We^T [e][n][k]
__device__ float    g_partial[2][(size_t)NTOK * OO];    // [slot][token][o]

// ---------------- PTX helpers ----------------
__device__ __forceinline__ uint32_t cvt_tf32(float v) {
    uint32_t r;
    asm("cvt.rna.tf32.f32 %0, %1;" : "=r"(r) : "f"(v));
    return r;
}
#define CP_ASYNC16(dst, src) \
    asm volatile("cp.async.cg.shared.global [%0], [%1], 16;" :: "r"(dst), "l"(src) : "memory")
#define CP_COMMIT() asm volatile("cp.async.commit_group;" ::: "memory")
#define CP_WAIT1()  asm volatile("cp.async.wait_group 1;" ::: "memory")
#define CP_WAIT0()  asm volatile("cp.async.wait_group 0;" ::: "memory")

__device__ __forceinline__ uint32_t smem_to_u32(const void* p) {
    uint32_t a;
    asm("{ .reg .u64 t; cvta.to.shared.u64 t, %1; cvt.u32.u64 %0, t; }" : "=r"(a) : "l"(p));
    return a;
}

#define LDSM_X4(r, addr) \
    asm volatile("ldmatrix.sync.aligned.m8n8.x4.shared.b16 {%0,%1,%2,%3}, [%4];" \
        : "=r"((r)[0]), "=r"((r)[1]), "=r"((r)[2]), "=r"((r)[3]) : "r"(addr))

#define MMA_TF32(d, a, b0, b1) \
    asm volatile("mma.sync.aligned.m16n8k8.row.col.f32.tf32.tf32.f32 " \
        "{%0,%1,%2,%3},{%4,%5,%6,%7},{%8,%9},{%0,%1,%2,%3};" \
        : "+f"((d)[0]), "+f"((d)[1]), "+f"((d)[2]), "+f"((d)[3]) \
        : "r"((a)[0]), "r"((a)[1]), "r"((a)[2]), "r"((a)[3]), "r"(b0), "r"(b1))

// ---------------- kernel 1: gating (R11 proven: 128 blocks, 64 tok/block) ----------------
__global__ __launch_bounds__(256) void gating_round_kernel(
    const float* __restrict__ x, const float* __restrict__ Wg)
{
    extern __shared__ float sdyn[];
    float* sWg = sdyn;                 // DD*EE floats (32 KB), layout [d][e]
    float* sX  = sdyn + DD * EE;       // 8 warps x DD floats (32 KB)

    const int tok0 = blockIdx.x * 64;
    const int task = tok0 / NN;

    const float4* wg4 = (const float4*)(Wg + (size_t)task * DD * EE);
    for (int i = threadIdx.x; i < DD * EE / 4; i += 256)
        ((float4*)sWg)[i] = wg4[i];
    __syncthreads();

    const int warp = threadIdx.x >> 5;
    const int lane = threadIdx.x & 31;
    float* myX = sX + warp * DD;

    for (int j = 0; j < 8; ++j) {
        const int token = tok0 + warp * 8 + j;
        const float4* x4 = (const float4*)(x + (size_t)token * DD);

        __syncwarp();
#pragma unroll
        for (int i = 0; i < 8; ++i) {
            const int idx = i * 32 + lane;
            const float4 v = x4[idx];
            uint4 t;
            t.x = cvt_tf32(v.x); t.y = cvt_tf32(v.y);
            t.z = cvt_tf32(v.z); t.w = cvt_tf32(v.w);
            *(uint4*)(g_xt + (size_t)token * DD + idx * 4) = t;
            *(float4*)&myX[idx * 4] = v;
        }
        __syncwarp();

        float acc[EE];
#pragma unroll
        for (int e = 0; e < EE; ++e) acc[e] = 0.0f;
#pragma unroll 4
        for (int it = 0; it < 32; ++it) {
            const int d = lane + 32 * it;
            const float xv = myX[d];
            const float4 w0 = *(const float4*)&sWg[d * EE];
            const float4 w1 = *(const float4*)&sWg[d * EE + 4];
            acc[0] += xv * w0.x; acc[1] += xv * w0.y;
            acc[2] += xv * w0.z; acc[3] += xv * w0.w;
            acc[4] += xv * w1.x; acc[5] += xv * w1.y;
            acc[6] += xv * w1.z; acc[7] += xv * w1.w;
        }

#pragma unroll
        for (int off = 16; off; off >>= 1)
#pragma unroll
            for (int e = 0; e < EE; ++e)
                acc[e] += __shfl_xor_sync(0xFFFFFFFFu, acc[e], off);

        if (lane == 0) {
            int e0 = 0;
#pragma unroll
            for (int e = 1; e < EE; ++e) if (acc[e] > acc[e0]) e0 = e;
            int e1 = (e0 == 0) ? 1 : 0;
#pragma unroll
            for (int e = 0; e < EE; ++e)
                if (e != e0 && e != e1 && acc[e] > acc[e1]) e1 = e;

            const float denom = acc[e0] + acc[e1] + 1e-9f;
            int p0 = atomicAdd(&g_count[e0], 1);
            g_tok[e0][p0] = token; g_slot[e0][p0] = 0; g_gate[e0][p0] = acc[e0] / denom;
            int p1 = atomicAdd(&g_count[e1], 1);
            g_tok[e1][p1] = token; g_slot[e1][p1] = 1; g_gate[e1][p1] = acc[e1] / denom;
        }
    }
}

// ---------------- kernel 2: transpose + tf32 round We, 64x64 tiles, full-width sectors ----------------
__global__ __launch_bounds__(256) void convert_w_kernel(const float* __restrict__ We) {
    __shared__ float tile[64][65];
    const int e  = blockIdx.z;
    const int n0 = blockIdx.x * 64;
    const int k0 = blockIdx.y * 64;
    const int tid = threadIdx.x;

    // load 64 rows x 64 floats: 1024 float4, 4 per thread, 2 x 256B per warp
#pragma unroll
    for (int it = 0; it < 4; ++it) {
        const int i   = tid + 256 * it;
        const int row = i >> 4;
        const int c4  = (i & 15) * 4;
        const float4 v = *(const float4*)&We[((size_t)e * DD + k0 + row) * OO + n0 + c4];
        tile[row][c4]     = v.x; tile[row][c4 + 1] = v.y;
        tile[row][c4 + 2] = v.z; tile[row][c4 + 3] = v.w;
    }
    __syncthreads();

    // transpose out: thread -> (n = tid/4, k-chunk = 16*(tid%4)); uint4 stores
    const int n  = tid >> 2;
    const int kc = (tid & 3) * 16;
    uint32_t* dst = g_wt + ((size_t)e * OO + n0 + n) * DD + k0 + kc;
#pragma unroll
    for (int j = 0; j < 4; ++j) {
        uint4 p;
        p.x = cvt_tf32(tile[kc + 4 * j][n]);
        p.y = cvt_tf32(tile[kc + 4 * j + 1][n]);
        p.z = cvt_tf32(tile[kc + 4 * j + 2][n]);
        p.w = cvt_tf32(tile[kc + 4 * j + 3][n]);
        *(uint4*)(dst + 4 * j) = p;
    }
}

// ---------------- kernel 3: gathered expert GEMM (R11 proven, untouched) ----------------
__device__ __forceinline__ void load_stage(uint32_t st, int k0, int e, int n0,
                                           const int* stok, int tid)
{
#pragma unroll
    for (int i = tid; i < 1024; i += NTHREADS) {
        const int row = i >> 3, cc = i & 7;
        CP_ASYNC16(st + (uint32_t)(row * ROWB + cc * 16),
                   g_xt + (size_t)stok[row] * DD + k0 + cc * 4);
    }
    const size_t bbase = ((size_t)e * OO + n0) * DD + k0;
#pragma unroll
    for (int i = tid; i < 1024; i += NTHREADS) {
        const int row = i >> 3, cc = i & 7;
        CP_ASYNC16(st + OFF_B + (uint32_t)(row * ROWB + cc * 16),
                   g_wt + bbase + (size_t)row * DD + cc * 4);
    }
    CP_COMMIT();
}

__global__ __launch_bounds__(NTHREADS, 2) void expert_gemm_tf32()
{
    extern __shared__ char smem[];
    const int e  = blockIdx.z;
    const int c  = g_count[e];
    const int m0 = blockIdx.y * BM;
    if (m0 >= c) return;
    const int n0 = blockIdx.x * BN;

    const int tid  = threadIdx.x;
    const int lane = tid & 31;
    const int wid  = tid >> 5;
    const int mw   = wid & 3;
    const int nw   = wid >> 2;
    const int grp  = lane >> 2;
    const int thr  = lane & 3;

    const uint32_t sb = smem_to_u32(smem);
    int*   stok  = (int*)smem;
    float* sgate = (float*)(smem + 512);
    int*   sslot = (int*)(smem + 1024);

    if (tid < BM) {
        const int m = m0 + tid;
        if (m < c) { stok[tid] = g_tok[e][m]; sgate[tid] = g_gate[e][m]; sslot[tid] = g_slot[e][m]; }
        else       { stok[tid] = 0;           sgate[tid] = 0.0f;         sslot[tid] = 0; }
    }
    __syncthreads();

    const uint32_t stage0 = sb + HDR_BYTES;
    load_stage(stage0,               0,  e, n0, stok, tid);
    load_stage(stage0 + STAGE_BYTES, BK, e, n0, stok, tid);

    const uint32_t aBase = stage0
        + (uint32_t)((32 * mw + (lane & 7) + 8 * ((lane >> 3) & 1)) * ROWB)
        + (uint32_t)((lane >> 4) * 16);
    const uint32_t bBase = stage0 + OFF_B
        + (uint32_t)((64 * nw + (lane & 7) + 8 * (lane >> 4)) * ROWB)
        + (uint32_t)(((lane >> 3) & 1) * 16);

    float acc[2][8][4];
#pragma unroll
    for (int t = 0; t < 2; ++t)
#pragma unroll
        for (int j = 0; j < 8; ++j)
#pragma unroll
            for (int z = 0; z < 4; ++z) acc[t][j][z] = 0.0f;

    uint32_t soff = 0;
    for (int ck = 0; ck < NCHUNK; ++ck) {
        if (ck < NCHUNK - 1) CP_WAIT1(); else CP_WAIT0();
        __syncthreads();

        if (ck + 2 < NCHUNK) {
            uint32_t s2 = soff + 2 * STAGE_BYTES;
            if (s2 >= (uint32_t)(NSTAGE * STAGE_BYTES)) s2 -= NSTAGE * STAGE_BYTES;
            load_stage(stage0 + s2, (ck + 2) * BK, e, n0, stok, tid);
        }

        const uint32_t aB = aBase + soff;
        const uint32_t bB = bBase + soff;

#pragma unroll
        for (int ks = 0; ks < 4; ++ks) {
            const uint32_t kb = (uint32_t)(ks * 32);
            uint32_t a[2][4], b[8][2];
            LDSM_X4(a[0], aB + kb);
            LDSM_X4(a[1], aB + 16 * ROWB + kb);
#pragma unroll
            for (int jj = 0; jj < 4; ++jj) {
                uint32_t r[4];
                LDSM_X4(r, bB + (uint32_t)(jj * 16 * ROWB) + kb);
                b[2 * jj][0]     = r[0]; b[2 * jj][1]     = r[1];
                b[2 * jj + 1][0] = r[2]; b[2 * jj + 1][1] = r[3];
            }
#pragma unroll
            for (int t = 0; t < 2; ++t)
#pragma unroll
                for (int j = 0; j < 8; ++j)
                    MMA_TF32(acc[t][j], a[t], b[j][0], b[j][1]);
        }

        soff += STAGE_BYTES;
        if (soff >= (uint32_t)(NSTAGE * STAGE_BYTES)) soff = 0;
    }

    // ---- epilogue: restage C through smem, coalesced float4 stores ----
    __syncthreads();
    float* sC = (float*)(smem + HDR_BYTES);
#pragma unroll
    for (int t = 0; t < 2; ++t) {
#pragma unroll
        for (int h = 0; h < 2; ++h) {
            const int r = 32 * mw + 16 * t + grp + 8 * h;
#pragma unroll
            for (int j = 0; j < 8; ++j) {
                float2 v = make_float2(acc[t][j][2 * h], acc[t][j][2 * h + 1]);
                *(float2*)&sC[r * 132 + 64 * nw + 8 * j + 2 * thr] = v;
            }
        }
    }
    __syncthreads();

#pragma unroll
    for (int rr = 0; rr < 16; ++rr) {
        const int row = wid * 16 + rr;
        if (m0 + row < c) {
            const float g = sgate[row];
            const float* src = &sC[row * 132 + lane * 4];
            float4 v = make_float4(src[0] * g, src[1] * g, src[2] * g, src[3] * g);
            float* dst = g_partial[sslot[row]] + (size_t)stok[row] * OO + n0 + lane * 4;
            *(float4*)dst = v;
        }
    }
}

// ---------------- kernel 4: combine the two slots + reset counts for next run ----------------
__global__ __launch_bounds__(256) void combine_kernel(float* __restrict__ out) {
    if (blockIdx.x == 0 && threadIdx.x < EE) g_count[threadIdx.x] = 0;
    const size_t i = (size_t)blockIdx.x * 256 + threadIdx.x;
    const float4 a = ((const float4*)g_partial[0])[i];
    const float4 b = ((const float4*)g_partial[1])[i];
    float4 r;
    r.x = a.x + b.x; r.y = a.y + b.y; r.z = a.z + b.z; r.w = a.w + b.w;
    ((float4*)out)[i] = r;
}

// ---------------- launch: fork/join so gating and convert_w run concurrently ----------------
extern "C" void kernel_launch(void* const* d_in, const int* in_sizes, int n_in,
                              void* d_out, int out_size)
{
    const float* x  = (const float*)d_in[0];   // [T, N, D]
    const float* Wg = (const float*)d_in[1];   // [T, D, E]
    const float* We = (const float*)d_in[2];   // [E, D, O]
    float* out = (float*)d_out;                // [T, N, O]

    static cudaStream_t s2 = nullptr;
    static cudaEvent_t  evFork = nullptr, evJoin = nullptr;
    if (s2 == nullptr) {
        cudaStreamCreateWithFlags(&s2, cudaStreamNonBlocking);
        cudaEventCreateWithFlags(&evFork, cudaEventDisableTiming);
        cudaEventCreateWithFlags(&evJoin, cudaEventDisableTiming);
        cudaFuncSetAttribute(gating_round_kernel,
                             cudaFuncAttributeMaxDynamicSharedMemorySize, GATE_SMEM);
        cudaFuncSetAttribute(expert_gemm_tf32,
                             cudaFuncAttributeMaxDynamicSharedMemorySize, SMEM_TOTAL);
    }

    // fork: convert_w enqueued FIRST so its branch starts immediately
    cudaEventRecord(evFork, 0);
    cudaStreamWaitEvent(s2, evFork, 0);
    {
        dim3 g(OO / 64, DD / 64, EE);   // (16, 16, 8) = 2048 blocks
        convert_w_kernel<<<g, 256, 0, s2>>>(We);
    }
    gating_round_kernel<<<NTOK / 64, 256, GATE_SMEM>>>(x, Wg);

    // join: GEMM depends on both branches
    cudaEventRecord(evJoin, s2);
    cudaStreamWaitEvent(0, evJoin, 0);

    dim3 grid(OO / BN, NTOK / BM, EE);   // (8, 64, 8); inactive tiles exit early
    expert_gemm_tf32<<<grid, NTHREADS, SMEM_TOTAL>>>();

    combine_kernel<<<(NTOK * OO / 4) / 256, 256>>>(out);
}

// round 15
// speedup vs baseline: 1.1488x; 1.1488x over previous
#include <cuda_runtime.h>
#include <cuda_bf16.h>
#include <cstdint>

#define TT 2
#define NN 4096
#define DD 1024
#define EE 8
#define OO 1024
#define NTOK (TT * NN)

// GEMM tiling: CTA 128x128, 8 warps of 32x64, BK=32, tf32, 2 CTAs/SM
#define BM 128
#define BN 128
#define BK 32
#define NCHUNK (DD / BK)       // 32
#define NTHREADS 256

#define ROWB 144               // 128B data + 16B pad -> conflict-free ldmatrix
#define OFF_B 18432            // A region = 128*144
#define STAGE_BYTES 36864
#define NSTAGE 3
#define HDR_BYTES 2048
#define SMEM_TOTAL (HDR_BYTES + NSTAGE * STAGE_BYTES)   // 112640 -> 2 CTAs/SM

#define GATE_SMEM ((DD * EE + 8 * DD) * 4)              // 65536: sWg + sX[8][DD]

// ---------------- device scratch ----------------
__device__ int      g_count[EE];                        // zeroed by combine tail each run
__device__ int      g_tok[EE][NTOK];
__device__ int      g_slot[EE][NTOK];
__device__ float    g_gate[EE][NTOK];
__device__ uint32_t g_xt[(size_t)NTOK * DD];            // tf32-rounded x  [token][k]
__device__ uint32_t g_wt[(size_t)EE * OO * DD];         // tf32-rounded We^T [e][n][k]
__device__ float    g_partial[2][(size_t)NTOK * OO];    // [slot][token][o]

// ---------------- PTX helpers ----------------
__device__ __forceinline__ uint32_t cvt_tf32(float v) {
    uint32_t r;
    asm("cvt.rna.tf32.f32 %0, %1;" : "=r"(r) : "f"(v));
    return r;
}
#define CP_ASYNC16(dst, src) \
    asm volatile("cp.async.cg.shared.global [%0], [%1], 16;" :: "r"(dst), "l"(src) : "memory")
#define CP_COMMIT() asm volatile("cp.async.commit_group;" ::: "memory")
#define CP_WAIT1()  asm volatile("cp.async.wait_group 1;" ::: "memory")
#define CP_WAIT0()  asm volatile("cp.async.wait_group 0;" ::: "memory")

__device__ __forceinline__ uint32_t smem_to_u32(const void* p) {
    uint32_t a;
    asm("{ .reg .u64 t; cvta.to.shared.u64 t, %1; cvt.u32.u64 %0, t; }" : "=r"(a) : "l"(p));
    return a;
}

#define LDSM_X4(r, addr) \
    asm volatile("ldmatrix.sync.aligned.m8n8.x4.shared.b16 {%0,%1,%2,%3}, [%4];" \
        : "=r"((r)[0]), "=r"((r)[1]), "=r"((r)[2]), "=r"((r)[3]) : "r"(addr))

#define MMA_TF32(d, a, b0, b1) \
    asm volatile("mma.sync.aligned.m16n8k8.row.col.f32.tf32.tf32.f32 " \
        "{%0,%1,%2,%3},{%4,%5,%6,%7},{%8,%9},{%0,%1,%2,%3};" \
        : "+f"((d)[0]), "+f"((d)[1]), "+f"((d)[2]), "+f"((d)[3]) \
        : "r"((a)[0]), "r"((a)[1]), "r"((a)[2]), "r"((a)[3]), "r"(b0), "r"(b1))

// ---------------- kernel 1: gating (R11 proven: 128 blocks, 64 tok/block) ----------------
__global__ __launch_bounds__(256) void gating_round_kernel(
    const float* __restrict__ x, const float* __restrict__ Wg)
{
    extern __shared__ float sdyn[];
    float* sWg = sdyn;                 // DD*EE floats (32 KB), layout [d][e]
    float* sX  = sdyn + DD * EE;       // 8 warps x DD floats (32 KB)

    const int tok0 = blockIdx.x * 64;
    const int task = tok0 / NN;

    const float4* wg4 = (const float4*)(Wg + (size_t)task * DD * EE);
    for (int i = threadIdx.x; i < DD * EE / 4; i += 256)
        ((float4*)sWg)[i] = wg4[i];
    __syncthreads();

    const int warp = threadIdx.x >> 5;
    const int lane = threadIdx.x & 31;
    float* myX = sX + warp * DD;

    for (int j = 0; j < 8; ++j) {
        const int token = tok0 + warp * 8 + j;
        const float4* x4 = (const float4*)(x + (size_t)token * DD);

        __syncwarp();
#pragma unroll
        for (int i = 0; i < 8; ++i) {
            const int idx = i * 32 + lane;
            const float4 v = x4[idx];
            uint4 t;
            t.x = cvt_tf32(v.x); t.y = cvt_tf32(v.y);
            t.z = cvt_tf32(v.z); t.w = cvt_tf32(v.w);
            *(uint4*)(g_xt + (size_t)token * DD + idx * 4) = t;
            *(float4*)&myX[idx * 4] = v;
        }
        __syncwarp();

        float acc[EE];
#pragma unroll
        for (int e = 0; e < EE; ++e) acc[e] = 0.0f;
#pragma unroll 4
        for (int it = 0; it < 32; ++it) {
            const int d = lane + 32 * it;
            const float xv = myX[d];
            const float4 w0 = *(const float4*)&sWg[d * EE];
            const float4 w1 = *(const float4*)&sWg[d * EE + 4];
            acc[0] += xv * w0.x; acc[1] += xv * w0.y;
            acc[2] += xv * w0.z; acc[3] += xv * w0.w;
            acc[4] += xv * w1.x; acc[5] += xv * w1.y;
            acc[6] += xv * w1.z; acc[7] += xv * w1.w;
        }

#pragma unroll
        for (int off = 16; off; off >>= 1)
#pragma unroll
            for (int e = 0; e < EE; ++e)
                acc[e] += __shfl_xor_sync(0xFFFFFFFFu, acc[e], off);

        if (lane == 0) {
            int e0 = 0;
#pragma unroll
            for (int e = 1; e < EE; ++e) if (acc[e] > acc[e0]) e0 = e;
            int e1 = (e0 == 0) ? 1 : 0;
#pragma unroll
            for (int e = 0; e < EE; ++e)
                if (e != e0 && e != e1 && acc[e] > acc[e1]) e1 = e;

            const float denom = acc[e0] + acc[e1] + 1e-9f;
            int p0 = atomicAdd(&g_count[e0], 1);
            g_tok[e0][p0] = token; g_slot[e0][p0] = 0; g_gate[e0][p0] = acc[e0] / denom;
            int p1 = atomicAdd(&g_count[e1], 1);
            g_tok[e1][p1] = token; g_slot[e1][p1] = 1; g_gate[e1][p1] = acc[e1] / denom;
        }
    }
}

// ---------------- kernel 2: transpose + tf32 round We, 64x64 tiles, full-width sectors ----------------
__global__ __launch_bounds__(256) void convert_w_kernel(const float* __restrict__ We) {
    __shared__ float tile[64][65];
    const int e  = blockIdx.z;
    const int n0 = blockIdx.x * 64;
    const int k0 = blockIdx.y * 64;
    const int tid = threadIdx.x;

#pragma unroll
    for (int it = 0; it < 4; ++it) {
        const int i   = tid + 256 * it;
        const int row = i >> 4;
        const int c4  = (i & 15) * 4;
        const float4 v = *(const float4*)&We[((size_t)e * DD + k0 + row) * OO + n0 + c4];
        tile[row][c4]     = v.x; tile[row][c4 + 1] = v.y;
        tile[row][c4 + 2] = v.z; tile[row][c4 + 3] = v.w;
    }
    __syncthreads();

    const int n  = tid >> 2;
    const int kc = (tid & 3) * 16;
    uint32_t* dst = g_wt + ((size_t)e * OO + n0 + n) * DD + k0 + kc;
#pragma unroll
    for (int j = 0; j < 4; ++j) {
        uint4 p;
        p.x = cvt_tf32(tile[kc + 4 * j][n]);
        p.y = cvt_tf32(tile[kc + 4 * j + 1][n]);
        p.z = cvt_tf32(tile[kc + 4 * j + 2][n]);
        p.w = cvt_tf32(tile[kc + 4 * j + 3][n]);
        *(uint4*)(dst + 4 * j) = p;
    }
}

// ---------------- kernel 3: gathered expert GEMM (R11 proven, untouched) ----------------
__device__ __forceinline__ void load_stage(uint32_t st, int k0, int e, int n0,
                                           const int* stok, int tid)
{
#pragma unroll
    for (int i = tid; i < 1024; i += NTHREADS) {
        const int row = i >> 3, cc = i & 7;
        CP_ASYNC16(st + (uint32_t)(row * ROWB + cc * 16),
                   g_xt + (size_t)stok[row] * DD + k0 + cc * 4);
    }
    const size_t bbase = ((size_t)e * OO + n0) * DD + k0;
#pragma unroll
    for (int i = tid; i < 1024; i += NTHREADS) {
        const int row = i >> 3, cc = i & 7;
        CP_ASYNC16(st + OFF_B + (uint32_t)(row * ROWB + cc * 16),
                   g_wt + bbase + (size_t)row * DD + cc * 4);
    }
    CP_COMMIT();
}

__global__ __launch_bounds__(NTHREADS, 2) void expert_gemm_tf32()
{
    extern __shared__ char smem[];
    const int e  = blockIdx.z;
    const int c  = g_count[e];
    const int m0 = blockIdx.y * BM;
    if (m0 >= c) return;
    const int n0 = blockIdx.x * BN;

    const int tid  = threadIdx.x;
    const int lane = tid & 31;
    const int wid  = tid >> 5;
    const int mw   = wid & 3;
    const int nw   = wid >> 2;
    const int grp  = lane >> 2;
    const int thr  = lane & 3;

    const uint32_t sb = smem_to_u32(smem);
    int*   stok  = (int*)smem;
    float* sgate = (float*)(smem + 512);
    int*   sslot = (int*)(smem + 1024);

    if (tid < BM) {
        const int m = m0 + tid;
        if (m < c) { stok[tid] = g_tok[e][m]; sgate[tid] = g_gate[e][m]; sslot[tid] = g_slot[e][m]; }
        else       { stok[tid] = 0;           sgate[tid] = 0.0f;         sslot[tid] = 0; }
    }
    __syncthreads();

    const uint32_t stage0 = sb + HDR_BYTES;
    load_stage(stage0,               0,  e, n0, stok, tid);
    load_stage(stage0 + STAGE_BYTES, BK, e, n0, stok, tid);

    const uint32_t aBase = stage0
        + (uint32_t)((32 * mw + (lane & 7) + 8 * ((lane >> 3) & 1)) * ROWB)
        + (uint32_t)((lane >> 4) * 16);
    const uint32_t bBase = stage0 + OFF_B
        + (uint32_t)((64 * nw + (lane & 7) + 8 * (lane >> 4)) * ROWB)
        + (uint32_t)(((lane >> 3) & 1) * 16);

    float acc[2][8][4];
#pragma unroll
    for (int t = 0; t < 2; ++t)
#pragma unroll
        for (int j = 0; j < 8; ++j)
#pragma unroll
            for (int z = 0; z < 4; ++z) acc[t][j][z] = 0.0f;

    uint32_t soff = 0;
    for (int ck = 0; ck < NCHUNK; ++ck) {
        if (ck < NCHUNK - 1) CP_WAIT1(); else CP_WAIT0();
        __syncthreads();

        if (ck + 2 < NCHUNK) {
            uint32_t s2 = soff + 2 * STAGE_BYTES;
            if (s2 >= (uint32_t)(NSTAGE * STAGE_BYTES)) s2 -= NSTAGE * STAGE_BYTES;
            load_stage(stage0 + s2, (ck + 2) * BK, e, n0, stok, tid);
        }

        const uint32_t aB = aBase + soff;
        const uint32_t bB = bBase + soff;

#pragma unroll
        for (int ks = 0; ks < 4; ++ks) {
            const uint32_t kb = (uint32_t)(ks * 32);
            uint32_t a[2][4], b[8][2];
            LDSM_X4(a[0], aB + kb);
            LDSM_X4(a[1], aB + 16 * ROWB + kb);
#pragma unroll
            for (int jj = 0; jj < 4; ++jj) {
                uint32_t r[4];
                LDSM_X4(r, bB + (uint32_t)(jj * 16 * ROWB) + kb);
                b[2 * jj][0]     = r[0]; b[2 * jj][1]     = r[1];
                b[2 * jj + 1][0] = r[2]; b[2 * jj + 1][1] = r[3];
            }
#pragma unroll
            for (int t = 0; t < 2; ++t)
#pragma unroll
                for (int j = 0; j < 8; ++j)
                    MMA_TF32(acc[t][j], a[t], b[j][0], b[j][1]);
        }

        soff += STAGE_BYTES;
        if (soff >= (uint32_t)(NSTAGE * STAGE_BYTES)) soff = 0;
    }

    // ---- epilogue: restage C through smem, coalesced float4 stores ----
    __syncthreads();
    float* sC = (float*)(smem + HDR_BYTES);
#pragma unroll
    for (int t = 0; t < 2; ++t) {
#pragma unroll
        for (int h = 0; h < 2; ++h) {
            const int r = 32 * mw + 16 * t + grp + 8 * h;
#pragma unroll
            for (int j = 0; j < 8; ++j) {
                float2 v = make_float2(acc[t][j][2 * h], acc[t][j][2 * h + 1]);
                *(float2*)&sC[r * 132 + 64 * nw + 8 * j + 2 * thr] = v;
            }
        }
    }
    __syncthreads();

#pragma unroll
    for (int rr = 0; rr < 16; ++rr) {
        const int row = wid * 16 + rr;
        if (m0 + row < c) {
            const float g = sgate[row];
            const float* src = &sC[row * 132 + lane * 4];
            float4 v = make_float4(src[0] * g, src[1] * g, src[2] * g, src[3] * g);
            float* dst = g_partial[sslot[row]] + (size_t)stok[row] * OO + n0 + lane * 4;
            *(float4*)dst = v;
        }
    }
}

// ---------------- kernel 4: combine the two slots + reset counts for next run ----------------
__global__ __launch_bounds__(256) void combine_kernel(float* __restrict__ out) {
    if (blockIdx.x == 0 && threadIdx.x < EE) g_count[threadIdx.x] = 0;
    const size_t i = (size_t)blockIdx.x * 256 + threadIdx.x;
    const float4 a = ((const float4*)g_partial[0])[i];
    const float4 b = ((const float4*)g_partial[1])[i];
    float4 r;
    r.x = a.x + b.x; r.y = a.y + b.y; r.z = a.z + b.z; r.w = a.w + b.w;
    ((float4*)out)[i] = r;
}

// ---------------- launch: fork/join, gating enqueued FIRST (R11 proven order) ----------------
extern "C" void kernel_launch(void* const* d_in, const int* in_sizes, int n_in,
                              void* d_out, int out_size)
{
    const float* x  = (const float*)d_in[0];   // [T, N, D]
    const float* Wg = (const float*)d_in[1];   // [T, D, E]
    const float* We = (const float*)d_in[2];   // [E, D, O]
    float* out = (float*)d_out;                // [T, N, O]

    static cudaStream_t s2 = nullptr;
    static cudaEvent_t  evFork = nullptr, evJoin = nullptr;
    if (s2 == nullptr) {
        cudaStreamCreateWithFlags(&s2, cudaStreamNonBlocking);
        cudaEventCreateWithFlags(&evFork, cudaEventDisableTiming);
        cudaEventCreateWithFlags(&evJoin, cudaEventDisableTiming);
        cudaFuncSetAttribute(gating_round_kernel,
                             cudaFuncAttributeMaxDynamicSharedMemorySize, GATE_SMEM);
        cudaFuncSetAttribute(expert_gemm_tf32,
                             cudaFuncAttributeMaxDynamicSharedMemorySize, SMEM_TOTAL);
    }

    // fork: gating (128 fat blocks) enqueued FIRST so it lands 1/SM;
    // convert_w backfills idle warp slots on s2
    cudaEventRecord(evFork, 0);
    cudaStreamWaitEvent(s2, evFork, 0);

    gating_round_kernel<<<NTOK / 64, 256, GATE_SMEM>>>(x, Wg);
    {
        dim3 g(OO / 64, DD / 64, EE);   // (16, 16, 8) = 2048 blocks
        convert_w_kernel<<<g, 256, 0, s2>>>(We);
    }

    // join: GEMM depends on both branches
    cudaEventRecord(evJoin, s2);
    cudaStreamWaitEvent(0, evJoin, 0);

    dim3 grid(OO / BN, NTOK / BM, EE);   // (8, 64, 8); inactive tiles exit early
    expert_gemm_tf32<<<grid, NTHREADS, SMEM_TOTAL>>>();

    combine_kernel<<<(NTOK * OO / 4) / 256, 256>>>(out);
}

// round 16
// speedup vs baseline: 1.1824x; 1.0293x over previous
#include <cuda_runtime.h>
#include <cuda_bf16.h>
#include <cstdint>

#define TT 2
#define NN 4096
#define DD 1024
#define EE 8
#define OO 1024
#define NTOK (TT * NN)

// GEMM tiling: CTA 128x128, 8 warps of 32x64, BK=32, tf32, 2 CTAs/SM
#define BM 128
#define BN 128
#define BK 32
#define NCHUNK (DD / BK)       // 32
#define NTHREADS 256

#define ROWB 144               // 128B data + 16B pad -> conflict-free ldmatrix
#define OFF_B 18432            // A region = 128*144
#define STAGE_BYTES 36864
#define NSTAGE 3
#define HDR_BYTES 2048
#define SMEM_TOTAL (HDR_BYTES + NSTAGE * STAGE_BYTES)   // 112640 -> 2 CTAs/SM

#define GATE_SMEM ((DD * EE + 8 * DD) * 4)              // 65536: sWg + sX[8][DD]

// combine geometry: 4 float4-pairs per thread, grid-strided
#define CMB_BLOCKS 2048
#define CMB_STRIDE (CMB_BLOCKS * 256)                   // 524288 float4 per pass

// ---------------- device scratch ----------------
__device__ int      g_count[EE];                        // zeroed by combine tail each run
__device__ int      g_tok[EE][NTOK];
__device__ int      g_slot[EE][NTOK];
__device__ float    g_gate[EE][NTOK];
__device__ uint32_t g_xt[(size_t)NTOK * DD];            // tf32-rounded x  [token][k]
__device__ uint32_t g_wt[(size_t)EE * OO * DD];         // tf32-rounded We^T [e][n][k]
__device__ float    g_partial[2][(size_t)NTOK * OO];    // [slot][token][o]

// ---------------- PTX helpers ----------------
__device__ __forceinline__ uint32_t cvt_tf32(float v) {
    uint32_t r;
    asm("cvt.rna.tf32.f32 %0, %1;" : "=r"(r) : "f"(v));
    return r;
}
#define CP_ASYNC16(dst, src) \
    asm volatile("cp.async.cg.shared.global [%0], [%1], 16;" :: "r"(dst), "l"(src) : "memory")
#define CP_COMMIT() asm volatile("cp.async.commit_group;" ::: "memory")
#define CP_WAIT1()  asm volatile("cp.async.wait_group 1;" ::: "memory")
#define CP_WAIT0()  asm volatile("cp.async.wait_group 0;" ::: "memory")

__device__ __forceinline__ uint32_t smem_to_u32(const void* p) {
    uint32_t a;
    asm("{ .reg .u64 t; cvta.to.shared.u64 t, %1; cvt.u32.u64 %0, t; }" : "=r"(a) : "l"(p));
    return a;
}

#define LDSM_X4(r, addr) \
    asm volatile("ldmatrix.sync.aligned.m8n8.x4.shared.b16 {%0,%1,%2,%3}, [%4];" \
        : "=r"((r)[0]), "=r"((r)[1]), "=r"((r)[2]), "=r"((r)[3]) : "r"(addr))

#define MMA_TF32(d, a, b0, b1) \
    asm volatile("mma.sync.aligned.m16n8k8.row.col.f32.tf32.tf32.f32 " \
        "{%0,%1,%2,%3},{%4,%5,%6,%7},{%8,%9},{%0,%1,%2,%3};" \
        : "+f"((d)[0]), "+f"((d)[1]), "+f"((d)[2]), "+f"((d)[3]) \
        : "r"((a)[0]), "r"((a)[1]), "r"((a)[2]), "r"((a)[3]), "r"(b0), "r"(b1))

// ---------------- kernel 1: gating (R11 proven: 128 blocks, 64 tok/block) ----------------
__global__ __launch_bounds__(256) void gating_round_kernel(
    const float* __restrict__ x, const float* __restrict__ Wg)
{
    extern __shared__ float sdyn[];
    float* sWg = sdyn;                 // DD*EE floats (32 KB), layout [d][e]
    float* sX  = sdyn + DD * EE;       // 8 warps x DD floats (32 KB)

    const int tok0 = blockIdx.x * 64;
    const int task = tok0 / NN;

    const float4* wg4 = (const float4*)(Wg + (size_t)task * DD * EE);
    for (int i = threadIdx.x; i < DD * EE / 4; i += 256)
        ((float4*)sWg)[i] = wg4[i];
    __syncthreads();

    const int warp = threadIdx.x >> 5;
    const int lane = threadIdx.x & 31;
    float* myX = sX + warp * DD;

    for (int j = 0; j < 8; ++j) {
        const int token = tok0 + warp * 8 + j;
        const float4* x4 = (const float4*)(x + (size_t)token * DD);

        __syncwarp();
#pragma unroll
        for (int i = 0; i < 8; ++i) {
            const int idx = i * 32 + lane;
            const float4 v = x4[idx];
            uint4 t;
            t.x = cvt_tf32(v.x); t.y = cvt_tf32(v.y);
            t.z = cvt_tf32(v.z); t.w = cvt_tf32(v.w);
            *(uint4*)(g_xt + (size_t)token * DD + idx * 4) = t;
            *(float4*)&myX[idx * 4] = v;
        }
        __syncwarp();

        float acc[EE];
#pragma unroll
        for (int e = 0; e < EE; ++e) acc[e] = 0.0f;
#pragma unroll 4
        for (int it = 0; it < 32; ++it) {
            const int d = lane + 32 * it;
            const float xv = myX[d];
            const float4 w0 = *(const float4*)&sWg[d * EE];
            const float4 w1 = *(const float4*)&sWg[d * EE + 4];
            acc[0] += xv * w0.x; acc[1] += xv * w0.y;
            acc[2] += xv * w0.z; acc[3] += xv * w0.w;
            acc[4] += xv * w1.x; acc[5] += xv * w1.y;
            acc[6] += xv * w1.z; acc[7] += xv * w1.w;
        }

#pragma unroll
        for (int off = 16; off; off >>= 1)
#pragma unroll
            for (int e = 0; e < EE; ++e)
                acc[e] += __shfl_xor_sync(0xFFFFFFFFu, acc[e], off);

        if (lane == 0) {
            int e0 = 0;
#pragma unroll
            for (int e = 1; e < EE; ++e) if (acc[e] > acc[e0]) e0 = e;
            int e1 = (e0 == 0) ? 1 : 0;
#pragma unroll
            for (int e = 0; e < EE; ++e)
                if (e != e0 && e != e1 && acc[e] > acc[e1]) e1 = e;

            const float denom = acc[e0] + acc[e1] + 1e-9f;
            int p0 = atomicAdd(&g_count[e0], 1);
            g_tok[e0][p0] = token; g_slot[e0][p0] = 0; g_gate[e0][p0] = acc[e0] / denom;
            int p1 = atomicAdd(&g_count[e1], 1);
            g_tok[e1][p1] = token; g_slot[e1][p1] = 1; g_gate[e1][p1] = acc[e1] / denom;
        }
    }
}

// ---------------- kernel 2: transpose + tf32 round We -> [e][n][k] (R11 proven) ----------------
__global__ void convert_w_kernel(const float* __restrict__ We) {
    __shared__ float tile[64][33];
    const int e  = blockIdx.z;
    const int n0 = blockIdx.x * 32;
    const int k0 = blockIdx.y * 64;
    const int tx = threadIdx.x, ty = threadIdx.y;

    for (int r = ty; r < 64; r += 8)
        tile[r][tx] = We[((size_t)e * DD + k0 + r) * OO + n0 + tx];
    __syncthreads();
#pragma unroll
    for (int s = 0; s < 4; ++s) {
        const int n = s * 8 + ty;
        uint2 p;
        p.x = cvt_tf32(tile[2 * tx][n]);
        p.y = cvt_tf32(tile[2 * tx + 1][n]);
        *(uint2*)(g_wt + ((size_t)e * OO + n0 + n) * DD + k0 + 2 * tx) = p;
    }
}

// ---------------- kernel 3: gathered expert GEMM (R11 proven, untouched) ----------------
__device__ __forceinline__ void load_stage(uint32_t st, int k0, int e, int n0,
                                           const int* stok, int tid)
{
#pragma unroll
    for (int i = tid; i < 1024; i += NTHREADS) {
        const int row = i >> 3, cc = i & 7;
        CP_ASYNC16(st + (uint32_t)(row * ROWB + cc * 16),
                   g_xt + (size_t)stok[row] * DD + k0 + cc * 4);
    }
    const size_t bbase = ((size_t)e * OO + n0) * DD + k0;
#pragma unroll
    for (int i = tid; i < 1024; i += NTHREADS) {
        const int row = i >> 3, cc = i & 7;
        CP_ASYNC16(st + OFF_B + (uint32_t)(row * ROWB + cc * 16),
                   g_wt + bbase + (size_t)row * DD + cc * 4);
    }
    CP_COMMIT();
}

__global__ __launch_bounds__(NTHREADS, 2) void expert_gemm_tf32()
{
    extern __shared__ char smem[];
    const int e  = blockIdx.z;
    const int c  = g_count[e];
    const int m0 = blockIdx.y * BM;
    if (m0 >= c) return;
    const int n0 = blockIdx.x * BN;

    const int tid  = threadIdx.x;
    const int lane = tid & 31;
    const int wid  = tid >> 5;
    const int mw   = wid & 3;
    const int nw   = wid >> 2;
    const int grp  = lane >> 2;
    const int thr  = lane & 3;

    const uint32_t sb = smem_to_u32(smem);
    int*   stok  = (int*)smem;
    float* sgate = (float*)(smem + 512);
    int*   sslot = (int*)(smem + 1024);

    if (tid < BM) {
        const int m = m0 + tid;
        if (m < c) { stok[tid] = g_tok[e][m]; sgate[tid] = g_gate[e][m]; sslot[tid] = g_slot[e][m]; }
        else       { stok[tid] = 0;           sgate[tid] = 0.0f;         sslot[tid] = 0; }
    }
    __syncthreads();

    const uint32_t stage0 = sb + HDR_BYTES;
    load_stage(stage0,               0,  e, n0, stok, tid);
    load_stage(stage0 + STAGE_BYTES, BK, e, n0, stok, tid);

    const uint32_t aBase = stage0
        + (uint32_t)((32 * mw + (lane & 7) + 8 * ((lane >> 3) & 1)) * ROWB)
        + (uint32_t)((lane >> 4) * 16);
    const uint32_t bBase = stage0 + OFF_B
        + (uint32_t)((64 * nw + (lane & 7) + 8 * (lane >> 4)) * ROWB)
        + (uint32_t)(((lane >> 3) & 1) * 16);

    float acc[2][8][4];
#pragma unroll
    for (int t = 0; t < 2; ++t)
#pragma unroll
        for (int j = 0; j < 8; ++j)
#pragma unroll
            for (int z = 0; z < 4; ++z) acc[t][j][z] = 0.0f;

    uint32_t soff = 0;
    for (int ck = 0; ck < NCHUNK; ++ck) {
        if (ck < NCHUNK - 1) CP_WAIT1(); else CP_WAIT0();
        __syncthreads();

        if (ck + 2 < NCHUNK) {
            uint32_t s2 = soff + 2 * STAGE_BYTES;
            if (s2 >= (uint32_t)(NSTAGE * STAGE_BYTES)) s2 -= NSTAGE * STAGE_BYTES;
            load_stage(stage0 + s2, (ck + 2) * BK, e, n0, stok, tid);
        }

        const uint32_t aB = aBase + soff;
        const uint32_t bB = bBase + soff;

#pragma unroll
        for (int ks = 0; ks < 4; ++ks) {
            const uint32_t kb = (uint32_t)(ks * 32);
            uint32_t a[2][4], b[8][2];
            LDSM_X4(a[0], aB + kb);
            LDSM_X4(a[1], aB + 16 * ROWB + kb);
#pragma unroll
            for (int jj = 0; jj < 4; ++jj) {
                uint32_t r[4];
                LDSM_X4(r, bB + (uint32_t)(jj * 16 * ROWB) + kb);
                b[2 * jj][0]     = r[0]; b[2 * jj][1]     = r[1];
                b[2 * jj + 1][0] = r[2]; b[2 * jj + 1][1] = r[3];
            }
#pragma unroll
            for (int t = 0; t < 2; ++t)
#pragma unroll
                for (int j = 0; j < 8; ++j)
                    MMA_TF32(acc[t][j], a[t], b[j][0], b[j][1]);
        }

        soff += STAGE_BYTES;
        if (soff >= (uint32_t)(NSTAGE * STAGE_BYTES)) soff = 0;
    }

    // ---- epilogue: restage C through smem, coalesced float4 stores ----
    __syncthreads();
    float* sC = (float*)(smem + HDR_BYTES);
#pragma unroll
    for (int t = 0; t < 2; ++t) {
#pragma unroll
        for (int h = 0; h < 2; ++h) {
            const int r = 32 * mw + 16 * t + grp + 8 * h;
#pragma unroll
            for (int j = 0; j < 8; ++j) {
                float2 v = make_float2(acc[t][j][2 * h], acc[t][j][2 * h + 1]);
                *(float2*)&sC[r * 132 + 64 * nw + 8 * j + 2 * thr] = v;
            }
        }
    }
    __syncthreads();

#pragma unroll
    for (int rr = 0; rr < 16; ++rr) {
        const int row = wid * 16 + rr;
        if (m0 + row < c) {
            const float g = sgate[row];
            const float* src = &sC[row * 132 + lane * 4];
            float4 v = make_float4(src[0] * g, src[1] * g, src[2] * g, src[3] * g);
            float* dst = g_partial[sslot[row]] + (size_t)stok[row] * OO + n0 + lane * 4;
            *(float4*)dst = v;
        }
    }
}

// ---------------- kernel 4: combine, 4 float4-pairs/thread, MLP-batched ----------------
__global__ __launch_bounds__(256) void combine_kernel(float* __restrict__ out) {
    if (blockIdx.x == 0 && threadIdx.x < EE) g_count[threadIdx.x] = 0;
    const size_t base = (size_t)blockIdx.x * 256 + threadIdx.x;
    const float4* p0 = (const float4*)g_partial[0];
    const float4* p1 = (const float4*)g_partial[1];
    float4* o4 = (float4*)out;

    float4 a[4], b[4];
#pragma unroll
    for (int k = 0; k < 4; ++k) a[k] = p0[base + (size_t)k * CMB_STRIDE];
#pragma unroll
    for (int k = 0; k < 4; ++k) b[k] = p1[base + (size_t)k * CMB_STRIDE];
#pragma unroll
    for (int k = 0; k < 4; ++k) {
        float4 r;
        r.x = a[k].x + b[k].x; r.y = a[k].y + b[k].y;
        r.z = a[k].z + b[k].z; r.w = a[k].w + b[k].w;
        o4[base + (size_t)k * CMB_STRIDE] = r;
    }
}

// ---------------- launch: fork/join, gating enqueued FIRST (R11 proven order) ----------------
extern "C" void kernel_launch(void* const* d_in, const int* in_sizes, int n_in,
                              void* d_out, int out_size)
{
    const float* x  = (const float*)d_in[0];   // [T, N, D]
    const float* Wg = (const float*)d_in[1];   // [T, D, E]
    const float* We = (const float*)d_in[2];   // [E, D, O]
    float* out = (float*)d_out;                // [T, N, O]

    static cudaStream_t s2 = nullptr;
    static cudaEvent_t  evFork = nullptr, evJoin = nullptr;
    if (s2 == nullptr) {
        cudaStreamCreateWithFlags(&s2, cudaStreamNonBlocking);
        cudaEventCreateWithFlags(&evFork, cudaEventDisableTiming);
        cudaEventCreateWithFlags(&evJoin, cudaEventDisableTiming);
        cudaFuncSetAttribute(gating_round_kernel,
                             cudaFuncAttributeMaxDynamicSharedMemorySize, GATE_SMEM);
        cudaFuncSetAttribute(expert_gemm_tf32,
                             cudaFuncAttributeMaxDynamicSharedMemorySize, SMEM_TOTAL);
    }

    // fork: gating (128 fat blocks) enqueued FIRST so it lands ~1/SM;
    // convert_w backfills idle warp slots on s2
    cudaEventRecord(evFork, 0);
    cudaStreamWaitEvent(s2, evFork, 0);

    gating_round_kernel<<<NTOK / 64, 256, GATE_SMEM>>>(x, Wg);
    {
        dim3 g(OO / 32, DD / 64, EE), b(32, 8);   // 4096 blocks (R11 proven)
        convert_w_kernel<<<g, b, 0, s2>>>(We);
    }

    // join: GEMM depends on both branches
    cudaEventRecord(evJoin, s2);
    cudaStreamWaitEvent(0, evJoin, 0);

    dim3 grid(OO / BN, NTOK / BM, EE);   // (8, 64, 8); inactive tiles exit early
    expert_gemm_tf32<<<grid, NTHREADS, SMEM_TOTAL>>>();

    combine_kernel<<<CMB_BLOCKS, 256>>>(out);
}